// round 4
// baseline (speedup 1.0000x reference)
#include <cuda_runtime.h>

// Problem constants
#define Cdim   16
#define CIN    18          // C + 2 (x_rel, y_rel)
#define Hh     128
#define Ww     128
#define HW     (Hh*Ww)     // 16384
#define Bb     4
#define Oo     32
#define BO     (Bb*Oo)     // 128
#define WTOT   593         // (C+2)*C + C + C*C + C + C + 1
#define TILES  32          // HW / PIXB
#define PIXB   512         // pixels per block
#define THREADS 128        // 4 pixels per thread
#define NB     (Bb*Oo*TILES)  // 4096 blocks total
#define NBLOCKS (BO*TILES)    // 4096

// Deterministic partial sums: layout [3 quantities][Bb][1024 per-b partials]
__device__ __align__(16) float g_part[3*NB];
__device__ unsigned int g_count = 0;

// ---------------- packed f32x2 helpers ----------------
__device__ __forceinline__ unsigned long long pack2f(float lo, float hi) {
    unsigned long long d;
    asm("mov.b64 %0, {%1, %2};" : "=l"(d)
        : "r"(__float_as_uint(lo)), "r"(__float_as_uint(hi)));
    return d;
}
__device__ __forceinline__ void unpack2f(unsigned long long v, float& lo, float& hi) {
    unsigned int a, b;
    asm("mov.b64 {%0, %1}, %2;" : "=r"(a), "=r"(b) : "l"(v));
    lo = __uint_as_float(a); hi = __uint_as_float(b);
}
__device__ __forceinline__ unsigned long long fma2(unsigned long long a,
                                                   unsigned long long b,
                                                   unsigned long long c) {
    unsigned long long d;
    asm("fma.rn.f32x2 %0, %1, %2, %3;" : "=l"(d) : "l"(a), "l"(b), "l"(c));
    return d;
}
__device__ __forceinline__ unsigned long long relu2(unsigned long long v) {
    float a, b; unpack2f(v, a, b);
    return pack2f(fmaxf(a, 0.0f), fmaxf(b, 0.0f));
}
__device__ __forceinline__ float warpRed(float v) {
    v += __shfl_xor_sync(0xffffffffu, v, 16);
    v += __shfl_xor_sync(0xffffffffu, v, 8);
    v += __shfl_xor_sync(0xffffffffu, v, 4);
    v += __shfl_xor_sync(0xffffffffu, v, 2);
    v += __shfl_xor_sync(0xffffffffu, v, 1);
    return v;
}

// ---------------- fused MLP + dice + finalize kernel ----------------
// Grid: x = bo (fast, interleaves masked/unmasked), y = tile
__global__ __launch_bounds__(THREADS)
void dice_mlp_kernel(const float* __restrict__ seg,
                     const float* __restrict__ cw,
                     const int*   __restrict__ mask,
                     const int*   __restrict__ ind,
                     const float* __restrict__ tgt,
                     float*       __restrict__ out) {
    const int bo   = blockIdx.x;           // b*Oo + o
    const int tile = blockIdx.y;
    const int b    = bo >> 5;
    const int tid  = threadIdx.x;
    // partial index within batch b: tile*32 + o  -> g_part layout [q][b][1024]
    const int bid  = b*1024 + tile*Oo + (bo & 31);

    __shared__ float4 s_w1q[CIN * 8];            // [c][k/2] -> (wk,wk,wk1,wk1)
    __shared__ float4 s_w2q[Cdim * 8];
    __shared__ unsigned long long s_b1p[16];
    __shared__ unsigned long long s_b2p[16];
    __shared__ unsigned long long s_w3p[16];
    __shared__ float s_b3;
    __shared__ float s_red[12];
    __shared__ int   s_last;

    const bool active = (mask[bo] != 0);

    if (active) {
        const int pos = ind[bo];
        {
            float* w1f = (float*)s_w1q;
            float* w2f = (float*)s_w2q;
            float* b1f = (float*)s_b1p;
            float* b2f = (float*)s_b2p;
            float* w3f = (float*)s_w3p;
            for (int i = tid; i < WTOT; i += THREADS) {
                float w = cw[((long)b*WTOT + i)*HW + pos];
                if (i < 288) {                       // w1: [k][c], k<16, c<18
                    int k = i / CIN, c = i % CIN;
                    int base = (c*8 + (k >> 1))*4 + (k & 1)*2;
                    w1f[base] = w; w1f[base + 1] = w;
                } else if (i < 304) {                // b1
                    int k = i - 288; b1f[2*k] = w; b1f[2*k + 1] = w;
                } else if (i < 560) {                // w2: [k][c], 16x16
                    int j = i - 304; int k = j >> 4, c = j & 15;
                    int base = (c*8 + (k >> 1))*4 + (k & 1)*2;
                    w2f[base] = w; w2f[base + 1] = w;
                } else if (i < 576) {                // b2
                    int k = i - 560; b2f[2*k] = w; b2f[2*k + 1] = w;
                } else if (i < 592) {                // w3
                    int k = i - 576; w3f[2*k] = w; w3f[2*k + 1] = w;
                } else {                             // b3
                    s_b3 = w;
                }
            }
        }
        __syncthreads();

        // This thread's 4 pixels (consecutive -> float4 loads, same row)
        const int p0 = tile*PIXB + tid*4;
        const int px = p0 & (Ww - 1);
        const int py = p0 >> 7;
        const float xi = (float)(pos & (Ww - 1));
        const float yi = (float)(pos >> 7);
        const float inv = 1.0f / 128.0f;
        const float xr0 = ((float)px - xi) * inv;
        const float yr  = ((float)py - yi) * inv;

        // Early target load: overlap DRAM latency with the MLP compute
        const float4 t = *(const float4*)(tgt + (long)bo*HW + p0);

        const ulonglong2* w1p = (const ulonglong2*)s_w1q;
        const ulonglong2* w2p = (const ulonglong2*)s_w2q;

        unsigned long long acc[2][16];
        // ---- layer 1: 18 -> 16 ----
#pragma unroll
        for (int k = 0; k < 16; k++) { acc[0][k] = s_b1p[k]; acc[1][k] = s_b1p[k]; }

        const float* segb = seg + (long)b*Cdim*HW;
        for (int c = 0; c < Cdim; c++) {
            float4 f = *(const float4*)(segb + c*HW + p0);
            unsigned long long f01 = pack2f(f.x, f.y);
            unsigned long long f23 = pack2f(f.z, f.w);
#pragma unroll
            for (int kk = 0; kk < 8; kk++) {
                ulonglong2 wv = w1p[c*8 + kk];
                acc[0][2*kk]     = fma2(wv.x, f01, acc[0][2*kk]);
                acc[1][2*kk]     = fma2(wv.x, f23, acc[1][2*kk]);
                acc[0][2*kk + 1] = fma2(wv.y, f01, acc[0][2*kk + 1]);
                acc[1][2*kk + 1] = fma2(wv.y, f23, acc[1][2*kk + 1]);
            }
        }
        {   // c = 16: x_rel
            unsigned long long f01 = pack2f(xr0,            xr0 +       inv);
            unsigned long long f23 = pack2f(xr0 + 2.0f*inv, xr0 + 3.0f*inv);
#pragma unroll
            for (int kk = 0; kk < 8; kk++) {
                ulonglong2 wv = w1p[16*8 + kk];
                acc[0][2*kk]     = fma2(wv.x, f01, acc[0][2*kk]);
                acc[1][2*kk]     = fma2(wv.x, f23, acc[1][2*kk]);
                acc[0][2*kk + 1] = fma2(wv.y, f01, acc[0][2*kk + 1]);
                acc[1][2*kk + 1] = fma2(wv.y, f23, acc[1][2*kk + 1]);
            }
        }
        {   // c = 17: y_rel (same for all 4 pixels)
            unsigned long long fy = pack2f(yr, yr);
#pragma unroll
            for (int kk = 0; kk < 8; kk++) {
                ulonglong2 wv = w1p[17*8 + kk];
                acc[0][2*kk]     = fma2(wv.x, fy, acc[0][2*kk]);
                acc[1][2*kk]     = fma2(wv.x, fy, acc[1][2*kk]);
                acc[0][2*kk + 1] = fma2(wv.y, fy, acc[0][2*kk + 1]);
                acc[1][2*kk + 1] = fma2(wv.y, fy, acc[1][2*kk + 1]);
            }
        }

        unsigned long long h1[2][16];
#pragma unroll
        for (int k = 0; k < 16; k++) { h1[0][k] = relu2(acc[0][k]); h1[1][k] = relu2(acc[1][k]); }

        // ---- layer 2: 16 -> 16 ----
#pragma unroll
        for (int k = 0; k < 16; k++) { acc[0][k] = s_b2p[k]; acc[1][k] = s_b2p[k]; }
        for (int c = 0; c < Cdim; c++) {
            unsigned long long f01 = h1[0][c];
            unsigned long long f23 = h1[1][c];
#pragma unroll
            for (int kk = 0; kk < 8; kk++) {
                ulonglong2 wv = w2p[c*8 + kk];
                acc[0][2*kk]     = fma2(wv.x, f01, acc[0][2*kk]);
                acc[1][2*kk]     = fma2(wv.x, f23, acc[1][2*kk]);
                acc[0][2*kk + 1] = fma2(wv.y, f01, acc[0][2*kk + 1]);
                acc[1][2*kk + 1] = fma2(wv.y, f23, acc[1][2*kk + 1]);
            }
        }

        // ---- layer 3: 16 -> 1, sigmoid, dice partials ----
        unsigned long long z01 = pack2f(s_b3, s_b3);
        unsigned long long z23 = z01;
#pragma unroll
        for (int k = 0; k < 16; k++) {
            z01 = fma2(s_w3p[k], relu2(acc[0][k]), z01);
            z23 = fma2(s_w3p[k], relu2(acc[1][k]), z23);
        }
        float z0, z1, z2, z3;
        unpack2f(z01, z0, z1);
        unpack2f(z23, z2, z3);

        float pr0 = 1.0f / (1.0f + __expf(-z0));
        float pr1 = 1.0f / (1.0f + __expf(-z1));
        float pr2 = 1.0f / (1.0f + __expf(-z2));
        float pr3 = 1.0f / (1.0f + __expf(-z3));

        float ai = pr0*t.x + pr1*t.y + pr2*t.z + pr3*t.w;
        float ap = pr0*pr0 + pr1*pr1 + pr2*pr2 + pr3*pr3;
        float at = t.x*t.x + t.y*t.y + t.z*t.z + t.w*t.w;

        // Block reduction (128 threads = 4 warps)
        ai = warpRed(ai); ap = warpRed(ap); at = warpRed(at);
        int wid = tid >> 5, lane = tid & 31;
        if (lane == 0) { s_red[wid] = ai; s_red[4 + wid] = ap; s_red[8 + wid] = at; }
        __syncthreads();
        if (tid == 0) {
            float I = s_red[0] + s_red[1] + s_red[2] + s_red[3];
            float P = s_red[4] + s_red[5] + s_red[6] + s_red[7];
            float T = s_red[8] + s_red[9] + s_red[10] + s_red[11];
            g_part[bid]        = I;
            g_part[NB  + bid]  = P;
            g_part[2*NB + bid] = T;
        }
    } else {
        if (tid == 0) {
            g_part[bid]        = 0.0f;
            g_part[NB  + bid]  = 0.0f;
            g_part[2*NB + bid] = 0.0f;
        }
    }

    // ---- last-block finalize (deterministic; counter self-resets for graph replay) ----
    if (tid == 0) {
        __threadfence();
        unsigned int ticket = atomicAdd(&g_count, 1u);
        s_last = (ticket == NBLOCKS - 1u) ? 1 : 0;
    }
    __syncthreads();
    if (!s_last) return;
    __threadfence();   // acquire: all other blocks' g_part stores now visible

    {
        const int w    = tid >> 5;   // warp 0..3
        const int lane = tid & 31;
        // 12 arrays (q*4+b) of 1024 partials each; warp w sums arrays w, w+4, w+8
#pragma unroll
        for (int a = w; a < 12; a += 4) {
            const float4* p4 = (const float4*)&g_part[a * 1024];
            float v = 0.0f;
#pragma unroll
            for (int i = 0; i < 8; i++) {
                float4 f = p4[lane + 32*i];
                v += (f.x + f.y) + (f.z + f.w);
            }
            v = warpRed(v);
            if (lane == 0) s_red[a] = v;
        }
    }
    __syncthreads();
    if (tid == 0) {
        float loss = 0.0f;
#pragma unroll
        for (int bb = 0; bb < Bb; bb++) {
            float I = s_red[bb];
            float P = s_red[4 + bb];
            float T = s_red[8 + bb];
            loss += 1.0f - (2.0f*I + 1.0f) / (P + T + 1.0f);
        }
        out[0]  = loss * 0.25f;
        g_count = 0;               // reset for next graph replay
    }
}

extern "C" void kernel_launch(void* const* d_in, const int* in_sizes, int n_in,
                              void* d_out, int out_size) {
    const float* seg  = (const float*)d_in[0];
    const float* cw   = (const float*)d_in[1];
    const int*   mask = (const int*)  d_in[2];
    const int*   ind  = (const int*)  d_in[3];
    const float* tgt  = (const float*)d_in[4];

    dim3 grid(BO, TILES);   // bo fast -> masked/unmasked interleaved per wave
    dice_mlp_kernel<<<grid, THREADS>>>(seg, cw, mask, ind, tgt, (float*)d_out);
}

// round 5
// speedup vs baseline: 1.1495x; 1.1495x over previous
#include <cuda_runtime.h>

// Problem constants
#define Cdim   16
#define CIN    18          // C + 2 (x_rel, y_rel)
#define Hh     128
#define Ww     128
#define HW     (Hh*Ww)     // 16384
#define Bb     4
#define Oo     32
#define BO     (Bb*Oo)     // 128
#define WTOT   593         // (C+2)*C + C + C*C + C + C + 1
#define TILES  32          // HW / PIXB
#define PIXB   512         // pixels per block
#define THREADS 128        // 4 pixels per thread
#define NB     (Bb*Oo*TILES)  // 4096 partials

// Deterministic partial sums: layout [3 quantities][Bb][1024 per-b partials]
__device__ __align__(16) float g_part[3*NB];

// ---------------- packed f32x2 helpers ----------------
__device__ __forceinline__ unsigned long long pack2f(float lo, float hi) {
    unsigned long long d;
    asm("mov.b64 %0, {%1, %2};" : "=l"(d)
        : "r"(__float_as_uint(lo)), "r"(__float_as_uint(hi)));
    return d;
}
__device__ __forceinline__ void unpack2f(unsigned long long v, float& lo, float& hi) {
    unsigned int a, b;
    asm("mov.b64 {%0, %1}, %2;" : "=r"(a), "=r"(b) : "l"(v));
    lo = __uint_as_float(a); hi = __uint_as_float(b);
}
__device__ __forceinline__ unsigned long long fma2(unsigned long long a,
                                                   unsigned long long b,
                                                   unsigned long long c) {
    unsigned long long d;
    asm("fma.rn.f32x2 %0, %1, %2, %3;" : "=l"(d) : "l"(a), "l"(b), "l"(c));
    return d;
}
__device__ __forceinline__ unsigned long long relu2(unsigned long long v) {
    float a, b; unpack2f(v, a, b);
    return pack2f(fmaxf(a, 0.0f), fmaxf(b, 0.0f));
}
__device__ __forceinline__ float warpRed(float v) {
    v += __shfl_xor_sync(0xffffffffu, v, 16);
    v += __shfl_xor_sync(0xffffffffu, v, 8);
    v += __shfl_xor_sync(0xffffffffu, v, 4);
    v += __shfl_xor_sync(0xffffffffu, v, 2);
    v += __shfl_xor_sync(0xffffffffu, v, 1);
    return v;
}

// ---------------- main MLP + dice-accumulate kernel ----------------
// Grid: x = bo (fast, interleaves masked/unmasked), y = tile
// __launch_bounds__(128, 4): cap regs at 128 -> 4 blocks/SM (16 warps)
__global__ __launch_bounds__(THREADS, 4)
void dice_mlp_kernel(const float* __restrict__ seg,
                     const float* __restrict__ cw,
                     const int*   __restrict__ mask,
                     const int*   __restrict__ ind,
                     const float* __restrict__ tgt) {
    const int bo   = blockIdx.x;           // b*Oo + o
    const int tile = blockIdx.y;
    const int b    = bo >> 5;
    const int tid  = threadIdx.x;
    // partial index within batch b: tile*32 + o  -> g_part layout [q][b][1024]
    const int bid  = b*1024 + tile*Oo + (bo & 31);

    // Masked-out (b,o): contributes nothing (pred*mask, tgt*mask both zero).
    if (mask[bo] == 0) {
        if (tid == 0) {
            g_part[bid]        = 0.0f;
            g_part[NB  + bid]  = 0.0f;
            g_part[2*NB + bid] = 0.0f;
        }
        return;
    }

    // Shared weights, duplicated-packed: each k stored as (w,w) so LDS.128
    // yields two broadcast-ready f32x2 operands.
    __shared__ float4 s_w1q[CIN * 8];            // [c][k/2] -> (wk,wk,wk1,wk1)
    __shared__ float4 s_w2q[Cdim * 8];
    __shared__ unsigned long long s_b1p[16];
    __shared__ unsigned long long s_b2p[16];
    __shared__ unsigned long long s_w3p[16];
    __shared__ float s_b3;
    __shared__ float s_red[12];

    const int pos = ind[bo];

    {
        float* w1f = (float*)s_w1q;
        float* w2f = (float*)s_w2q;
        float* b1f = (float*)s_b1p;
        float* b2f = (float*)s_b2p;
        float* w3f = (float*)s_w3p;
        for (int i = tid; i < WTOT; i += THREADS) {
            float w = cw[((long)b*WTOT + i)*HW + pos];
            if (i < 288) {                       // w1: [k][c], k<16, c<18
                int k = i / CIN, c = i % CIN;
                int base = (c*8 + (k >> 1))*4 + (k & 1)*2;
                w1f[base] = w; w1f[base + 1] = w;
            } else if (i < 304) {                // b1
                int k = i - 288; b1f[2*k] = w; b1f[2*k + 1] = w;
            } else if (i < 560) {                // w2: [k][c], 16x16
                int j = i - 304; int k = j >> 4, c = j & 15;
                int base = (c*8 + (k >> 1))*4 + (k & 1)*2;
                w2f[base] = w; w2f[base + 1] = w;
            } else if (i < 576) {                // b2
                int k = i - 560; b2f[2*k] = w; b2f[2*k + 1] = w;
            } else if (i < 592) {                // w3
                int k = i - 576; w3f[2*k] = w; w3f[2*k + 1] = w;
            } else {                             // b3
                s_b3 = w;
            }
        }
    }
    __syncthreads();

    // This thread's 4 pixels (consecutive -> float4 loads, same row)
    const int p0 = tile*PIXB + tid*4;
    const int px = p0 & (Ww - 1);
    const int py = p0 >> 7;
    const float xi = (float)(pos & (Ww - 1));
    const float yi = (float)(pos >> 7);
    const float inv = 1.0f / 128.0f;
    const float xr0 = ((float)px - xi) * inv;
    const float yr  = ((float)py - yi) * inv;

    const ulonglong2* w1p = (const ulonglong2*)s_w1q;
    const ulonglong2* w2p = (const ulonglong2*)s_w2q;

    // ---- layer 1: 18 -> 16 (acc becomes h1 in place) ----
    unsigned long long acc0[16], acc1[16];
#pragma unroll
    for (int k = 0; k < 16; k++) { acc0[k] = s_b1p[k]; acc1[k] = s_b1p[k]; }

    const float* segb = seg + (long)b*Cdim*HW;
    for (int c = 0; c < Cdim; c++) {
        float4 f = *(const float4*)(segb + c*HW + p0);
        unsigned long long f01 = pack2f(f.x, f.y);
        unsigned long long f23 = pack2f(f.z, f.w);
#pragma unroll
        for (int kk = 0; kk < 8; kk++) {
            ulonglong2 wv = w1p[c*8 + kk];
            acc0[2*kk]     = fma2(wv.x, f01, acc0[2*kk]);
            acc1[2*kk]     = fma2(wv.x, f23, acc1[2*kk]);
            acc0[2*kk + 1] = fma2(wv.y, f01, acc0[2*kk + 1]);
            acc1[2*kk + 1] = fma2(wv.y, f23, acc1[2*kk + 1]);
        }
    }
    {   // c = 16: x_rel
        unsigned long long f01 = pack2f(xr0,            xr0 +       inv);
        unsigned long long f23 = pack2f(xr0 + 2.0f*inv, xr0 + 3.0f*inv);
#pragma unroll
        for (int kk = 0; kk < 8; kk++) {
            ulonglong2 wv = w1p[16*8 + kk];
            acc0[2*kk]     = fma2(wv.x, f01, acc0[2*kk]);
            acc1[2*kk]     = fma2(wv.x, f23, acc1[2*kk]);
            acc0[2*kk + 1] = fma2(wv.y, f01, acc0[2*kk + 1]);
            acc1[2*kk + 1] = fma2(wv.y, f23, acc1[2*kk + 1]);
        }
    }
    {   // c = 17: y_rel (same for all 4 pixels)
        unsigned long long fy = pack2f(yr, yr);
#pragma unroll
        for (int kk = 0; kk < 8; kk++) {
            ulonglong2 wv = w1p[17*8 + kk];
            acc0[2*kk]     = fma2(wv.x, fy, acc0[2*kk]);
            acc1[2*kk]     = fma2(wv.x, fy, acc1[2*kk]);
            acc0[2*kk + 1] = fma2(wv.y, fy, acc0[2*kk + 1]);
            acc1[2*kk + 1] = fma2(wv.y, fy, acc1[2*kk + 1]);
        }
    }

    // relu in place: acc becomes h1
#pragma unroll
    for (int k = 0; k < 16; k++) { acc0[k] = relu2(acc0[k]); acc1[k] = relu2(acc1[k]); }

    // ---- layer 2 (16 -> 16) fused with layer 3 (16 -> 1), in k-halves of 8 ----
    unsigned long long z01 = pack2f(s_b3, s_b3);
    unsigned long long z23 = z01;
#pragma unroll 1
    for (int h = 0; h < 2; h++) {
        unsigned long long a20[8], a21[8];
#pragma unroll
        for (int k = 0; k < 8; k++) { a20[k] = s_b2p[h*8 + k]; a21[k] = a20[k]; }
        for (int c = 0; c < Cdim; c++) {
            unsigned long long f01 = acc0[c];
            unsigned long long f23 = acc1[c];
#pragma unroll
            for (int kk = 0; kk < 4; kk++) {
                ulonglong2 wv = w2p[c*8 + h*4 + kk];
                a20[2*kk]     = fma2(wv.x, f01, a20[2*kk]);
                a21[2*kk]     = fma2(wv.x, f23, a21[2*kk]);
                a20[2*kk + 1] = fma2(wv.y, f01, a20[2*kk + 1]);
                a21[2*kk + 1] = fma2(wv.y, f23, a21[2*kk + 1]);
            }
        }
#pragma unroll
        for (int k = 0; k < 8; k++) {
            z01 = fma2(s_w3p[h*8 + k], relu2(a20[k]), z01);
            z23 = fma2(s_w3p[h*8 + k], relu2(a21[k]), z23);
        }
    }

    // ---- sigmoid + dice partials ----
    float z0, z1, z2, z3;
    unpack2f(z01, z0, z1);
    unpack2f(z23, z2, z3);

    float pr0 = 1.0f / (1.0f + __expf(-z0));
    float pr1 = 1.0f / (1.0f + __expf(-z1));
    float pr2 = 1.0f / (1.0f + __expf(-z2));
    float pr3 = 1.0f / (1.0f + __expf(-z3));

    float4 t = *(const float4*)(tgt + (long)bo*HW + p0);

    float ai = pr0*t.x + pr1*t.y + pr2*t.z + pr3*t.w;
    float ap = pr0*pr0 + pr1*pr1 + pr2*pr2 + pr3*pr3;
    float at = t.x*t.x + t.y*t.y + t.z*t.z + t.w*t.w;

    // Block reduction (128 threads = 4 warps)
    ai = warpRed(ai); ap = warpRed(ap); at = warpRed(at);
    int wid = tid >> 5, lane = tid & 31;
    if (lane == 0) { s_red[wid] = ai; s_red[4 + wid] = ap; s_red[8 + wid] = at; }
    __syncthreads();
    if (tid == 0) {
        float I = s_red[0] + s_red[1] + s_red[2] + s_red[3];
        float P = s_red[4] + s_red[5] + s_red[6] + s_red[7];
        float T = s_red[8] + s_red[9] + s_red[10] + s_red[11];
        g_part[bid]        = I;
        g_part[NB  + bid]  = P;
        g_part[2*NB + bid] = T;
    }
}

// ---------------- deterministic finalize: 12 warps, one per (quantity,batch) ----------------
__global__ __launch_bounds__(384)
void dice_finalize_kernel(float* __restrict__ out) {
    __shared__ float s[12];
    const int w    = threadIdx.x >> 5;   // 0..11  == q*4 + b  (g_part is [12][1024])
    const int lane = threadIdx.x & 31;

    const float4* p4 = (const float4*)&g_part[w * 1024];
    float v = 0.0f;
#pragma unroll
    for (int i = 0; i < 8; i++) {
        float4 f = p4[lane + 32*i];
        v += (f.x + f.y) + (f.z + f.w);
    }
    v = warpRed(v);
    if (lane == 0) s[w] = v;
    __syncthreads();

    if (threadIdx.x == 0) {
        float loss = 0.0f;
#pragma unroll
        for (int b = 0; b < Bb; b++) {
            float I = s[b];
            float P = s[4 + b];
            float T = s[8 + b];
            loss += 1.0f - (2.0f*I + 1.0f) / (P + T + 1.0f);
        }
        out[0] = loss * 0.25f;
    }
}

extern "C" void kernel_launch(void* const* d_in, const int* in_sizes, int n_in,
                              void* d_out, int out_size) {
    const float* seg  = (const float*)d_in[0];
    const float* cw   = (const float*)d_in[1];
    const int*   mask = (const int*)  d_in[2];
    const int*   ind  = (const int*)  d_in[3];
    const float* tgt  = (const float*)d_in[4];

    dim3 grid(BO, TILES);   // bo fast -> masked/unmasked interleaved per wave
    dice_mlp_kernel<<<grid, THREADS>>>(seg, cw, mask, ind, tgt);
    dice_finalize_kernel<<<1, 384>>>((float*)d_out);
}